// round 7
// baseline (speedup 1.0000x reference)
#include <cuda_runtime.h>
#include <math.h>
#include <stdint.h>

#define BB 8
#define CIN 128
#define COUT 128
#define HH 64
#define WW 64
#define KHW 3
#define KK 9
#define PP 4096            // Ho*Wo
#define MK 1152            // Cin*K

// W transposed + tf32-rounded: g_wt[k][co]
__device__ float g_wt[(size_t)MK * COUT];

__device__ __forceinline__ uint32_t f2tf32(float f) {
    uint32_t r;
    asm("cvt.rna.tf32.f32 %0, %1;" : "=r"(r) : "f"(f));
    return r;
}

// Transpose + round W: g_wt[k][co] = tf32(W[co][k])
__global__ __launch_bounds__(256) void wprep_kernel(const float* __restrict__ Wt)
{
    int idx = blockIdx.x * blockDim.x + threadIdx.x;
    if (idx >= MK * COUT) return;
    int k  = idx >> 7;
    int co = idx & 127;
    g_wt[idx] = __uint_as_float(f2tf32(Wt[(size_t)co * MK + k]));
}

// ---------------------------------------------------------------------------
// Fused deformable-im2col + TF32 tensor-core GEMM.
// out[b][co][p] = sum_{c,k} W[co][c*9+k] * bilinear(input[b][c], pos(k,p)) * mask
// Block tile 128(co) x 128(p) x 16(m), 256 threads, warp tile 64x32.
// B tile is produced in-kernel from gathered input (no cols scratch).
// ---------------------------------------------------------------------------

#define BK 16
#define LDA 136                       // smem row stride (words)
#define TILE_WORDS (BK * LDA)         // 2176
#define NSTG_A 3
#define META_OFF_WORDS (KK * 128 * 2)   // uint2 per (k,p)
#define META_W_WORDS   (KK * 128 * 4)   // float4 per (k,p)
#define SMEM_WORDS (NSTG_A * TILE_WORDS + 2 * TILE_WORDS + META_OFF_WORDS + META_W_WORDS)
#define SMEM_BYTES (SMEM_WORDS * 4)     // 71168

__device__ __forceinline__ void cp16(uint32_t dst, const void* src) {
    asm volatile("cp.async.cg.shared.global [%0], [%1], 16;\n"
                 :: "r"(dst), "l"(src));
}

__global__ __launch_bounds__(256, 2) void fused_kernel(
    const float* __restrict__ input,
    const float* __restrict__ offset,
    const float* __restrict__ mask,
    const float* __restrict__ bias,
    float* __restrict__ out)
{
    extern __shared__ uint32_t smem[];
    uint32_t* As0   = smem;                                   // [3][BK][LDA]
    uint32_t* Bs0   = smem + NSTG_A * TILE_WORDS;             // [2][BK][LDA]
    uint2*    moff  = reinterpret_cast<uint2*>(smem + NSTG_A * TILE_WORDS + 2 * TILE_WORDS);
    float4*   mw    = reinterpret_cast<float4*>(smem + NSTG_A * TILE_WORDS + 2 * TILE_WORDS + META_OFF_WORDS);

    const int b  = blockIdx.z;
    const int n0 = blockIdx.x * 128;

    const int tid  = threadIdx.x;
    const int wid  = tid >> 5;
    const int lane = tid & 31;
    const int wm = wid & 1;
    const int wn = wid >> 1;
    const int m_base = wm * 64;
    const int n_base = wn * 32;
    const int qr = lane >> 2;
    const int qc = lane & 3;

    // A cp.async mapping (16 x 128 tile, 2 float4 per thread)
    const int ar = tid >> 5;          // 0..7
    const int ac = (tid & 31) * 4;    // 0..124

    // B fill mapping: row r within tile, 8 pixels stride-16
    const int br = tid >> 4;          // 0..15
    const int bc = tid & 15;          // pixel group

    uint32_t smem_u32 = (uint32_t)__cvta_generic_to_shared(smem);
    const uint32_t a_smem = smem_u32;
    const float* inb_base = input + (size_t)b * CIN * HH * WW;

    float acc[4][4][4];
    #pragma unroll
    for (int mi = 0; mi < 4; mi++)
        #pragma unroll
        for (int ni = 0; ni < 4; ni++)
            #pragma unroll
            for (int c = 0; c < 4; c++) acc[mi][ni][c] = 0.f;

    const int NK = MK / BK;   // 72

    auto issue_a = [&](int s, int kt) {
        uint32_t ad = a_smem + (uint32_t)(s * TILE_WORDS + ar * LDA + ac) * 4;
        const float* asrc = g_wt + (size_t)(kt + ar) * COUT + ac;
        cp16(ad,               asrc);
        cp16(ad + 8 * LDA * 4, asrc + (size_t)8 * COUT);
    };

    // kick off A stages 0,1 while we compute metadata
    issue_a(0, 0);
    asm volatile("cp.async.commit_group;\n");
    issue_a(1, BK);
    asm volatile("cp.async.commit_group;\n");

    // ---- metadata: for each (k, p_local): 4 corner offsets + 4 weights ----
    for (int idx = tid; idx < KK * 128; idx += 256) {
        int k  = idx >> 7;
        int pl = idx & 127;
        int p  = n0 + pl;
        int y  = p >> 6;
        int x  = p & 63;

        float offy = offset[((size_t)b * 2 * KK + 2 * k) * PP + p];
        float offx = offset[((size_t)b * 2 * KK + 2 * k + 1) * PP + p];
        float mval = mask[((size_t)b * KK + k) * PP + p];

        float py = offy + (float)(y - 1 + k / KHW);
        float px = offx + (float)(x - 1 + k % KHW);

        float y0f = floorf(py), x0f = floorf(px);
        float ly = py - y0f, lx = px - x0f;
        int y0 = (int)y0f, x0 = (int)x0f;
        int y1 = y0 + 1, x1 = x0 + 1;

        bool vy0 = (y0 >= 0) & (y0 < HH);
        bool vy1 = (y1 >= 0) & (y1 < HH);
        bool vx0 = (x0 >= 0) & (x0 < WW);
        bool vx1 = (x1 >= 0) & (x1 < WW);

        int cy0 = min(max(y0, 0), HH - 1), cy1 = min(max(y1, 0), HH - 1);
        int cx0 = min(max(x0, 0), WW - 1), cx1 = min(max(x1, 0), WW - 1);
        unsigned o00 = cy0 * WW + cx0, o01 = cy0 * WW + cx1;
        unsigned o10 = cy1 * WW + cx0, o11 = cy1 * WW + cx1;

        float w00 = (1.f - ly) * (1.f - lx) * ((vy0 & vx0) ? 1.f : 0.f) * mval;
        float w01 = (1.f - ly) * lx         * ((vy0 & vx1) ? 1.f : 0.f) * mval;
        float w10 = ly * (1.f - lx)         * ((vy1 & vx0) ? 1.f : 0.f) * mval;
        float w11 = ly * lx                 * ((vy1 & vx1) ? 1.f : 0.f) * mval;

        moff[idx] = make_uint2(o00 | (o01 << 16), o10 | (o11 << 16));
        mw[idx]   = make_float4(w00, w01, w10, w11);
    }
    __syncthreads();   // metadata visible

    auto fill_b = [&](int nb, int kt) {
        int m = kt + br;
        int c = m / 9;
        int k = m - 9 * c;
        const float* ic = inb_base + (size_t)c * HH * WW;
        uint32_t* dst = Bs0 + nb * TILE_WORDS + br * LDA;
        const uint2*  mo = moff + k * 128;
        const float4* mv = mw   + k * 128;
        #pragma unroll
        for (int j = 0; j < 8; j++) {
            int pl = bc + 16 * j;
            uint2  o  = mo[pl];
            float4 w  = mv[pl];
            float v = w.x * __ldg(ic + (o.x & 0xffff))
                    + w.y * __ldg(ic + (o.x >> 16))
                    + w.z * __ldg(ic + (o.y & 0xffff))
                    + w.w * __ldg(ic + (o.y >> 16));
            dst[pl] = f2tf32(v);
        }
    };

    fill_b(0, 0);
    __syncthreads();   // B0 ready

    for (int i = 0; i < NK; i++) {
        if (i + 2 < NK) issue_a((i + 2) % NSTG_A, (i + 2) * BK);
        asm volatile("cp.async.commit_group;\n");
        if (i + 1 < NK) fill_b((i + 1) & 1, (i + 1) * BK);
        asm volatile("cp.async.wait_group 2;\n");   // A stage i ready

        const uint32_t* As_ = As0 + (size_t)(i % NSTG_A) * TILE_WORDS;
        const uint32_t* Bs_ = Bs0 + (size_t)(i & 1) * TILE_WORDS;

        #pragma unroll
        for (int ks = 0; ks < 2; ks++) {
            const int k0 = ks * 8;
            uint32_t afr[4][4];
            uint32_t bfr[4][2];
            #pragma unroll
            for (int mi = 0; mi < 4; mi++) {
                int r = m_base + mi * 16 + qr;
                afr[mi][0] = As_[(k0 + qc) * LDA + r];
                afr[mi][1] = As_[(k0 + qc) * LDA + r + 8];
                afr[mi][2] = As_[(k0 + qc + 4) * LDA + r];
                afr[mi][3] = As_[(k0 + qc + 4) * LDA + r + 8];
            }
            #pragma unroll
            for (int ni = 0; ni < 4; ni++) {
                int cidx = n_base + ni * 8 + qr;
                bfr[ni][0] = Bs_[(k0 + qc) * LDA + cidx];
                bfr[ni][1] = Bs_[(k0 + qc + 4) * LDA + cidx];
            }
            #pragma unroll
            for (int mi = 0; mi < 4; mi++)
                #pragma unroll
                for (int ni = 0; ni < 4; ni++) {
                    asm volatile(
                        "mma.sync.aligned.m16n8k8.row.col.f32.tf32.tf32.f32 "
                        "{%0,%1,%2,%3}, {%4,%5,%6,%7}, {%8,%9}, {%0,%1,%2,%3};\n"
                        : "+f"(acc[mi][ni][0]), "+f"(acc[mi][ni][1]),
                          "+f"(acc[mi][ni][2]), "+f"(acc[mi][ni][3])
                        : "r"(afr[mi][0]), "r"(afr[mi][1]),
                          "r"(afr[mi][2]), "r"(afr[mi][3]),
                          "r"(bfr[ni][0]), "r"(bfr[ni][1]));
                }
        }
        __syncthreads();
    }

    // epilogue
    float* outb = out + (size_t)b * COUT * PP;
    const int cr = lane >> 2;
    const int cc = (lane & 3) * 2;
    #pragma unroll
    for (int mi = 0; mi < 4; mi++) {
        int row = m_base + mi * 16 + cr;
        float bv0 = bias[row];
        float bv1 = bias[row + 8];
        #pragma unroll
        for (int ni = 0; ni < 4; ni++) {
            int col = n0 + n_base + ni * 8 + cc;
            float2 v0 = make_float2(acc[mi][ni][0] + bv0, acc[mi][ni][1] + bv0);
            float2 v1 = make_float2(acc[mi][ni][2] + bv1, acc[mi][ni][3] + bv1);
            *reinterpret_cast<float2*>(outb + (size_t)row * PP + col)       = v0;
            *reinterpret_cast<float2*>(outb + (size_t)(row + 8) * PP + col) = v1;
        }
    }
}

extern "C" void kernel_launch(void* const* d_in, const int* in_sizes, int n_in,
                              void* d_out, int out_size)
{
    const float* input  = (const float*)d_in[0];
    const float* offset = (const float*)d_in[1];
    const float* mask   = (const float*)d_in[2];
    const float* weight = (const float*)d_in[3];
    const float* bias   = (const float*)d_in[4];
    float* out = (float*)d_out;

    wprep_kernel<<<(MK * COUT + 255) / 256, 256>>>(weight);

    cudaFuncSetAttribute(fused_kernel,
                         cudaFuncAttributeMaxDynamicSharedMemorySize, SMEM_BYTES);
    dim3 grid(PP / 128, 1, BB);               // (32, 1, 8)
    fused_kernel<<<grid, 256, SMEM_BYTES>>>(input, offset, mask, bias, out);
}

// round 9
// speedup vs baseline: 1.0419x; 1.0419x over previous
#include <cuda_runtime.h>
#include <math.h>
#include <stdint.h>

#define BB 8
#define CIN 128
#define COUT 128
#define HH 64
#define WW 64
#define KHW 3
#define KK 9
#define PP 4096            // Ho*Wo
#define MK 1152            // Cin*K

// W transposed + tf32-rounded: g_wt[k][co]
__device__ float g_wt[(size_t)MK * COUT];

__device__ __forceinline__ uint32_t f2tf32(float f) {
    uint32_t r;
    asm("cvt.rna.tf32.f32 %0, %1;" : "=r"(r) : "f"(f));
    return r;
}

// Transpose + round W: g_wt[k][co] = tf32(W[co][k])
__global__ __launch_bounds__(256) void wprep_kernel(const float* __restrict__ Wt)
{
    int idx = blockIdx.x * blockDim.x + threadIdx.x;
    if (idx >= MK * COUT) return;
    int k  = idx >> 7;
    int co = idx & 127;
    g_wt[idx] = __uint_as_float(f2tf32(Wt[(size_t)co * MK + k]));
}

// ---------------------------------------------------------------------------
// Fused deformable-im2col + TF32 GEMM, with split issue/consume B production:
// gathers for tile i+1 are issued before each MMA half-step of tile i and
// consumed (weighted, converted, stored) after it, so LDG latency hides
// under tensor work inside the same warp.
// ---------------------------------------------------------------------------

#define BK 16
#define LDA 136                       // smem row stride (words)
#define TILE_WORDS (BK * LDA)         // 2176
#define NSTG_A 3
#define META_OFF_WORDS (KK * 128 * 2)   // uint2 per (k,p)
#define META_W_WORDS   (KK * 128 * 4)   // float4 per (k,p)
#define SMEM_WORDS (NSTG_A * TILE_WORDS + 2 * TILE_WORDS + META_OFF_WORDS + META_W_WORDS)
#define SMEM_BYTES (SMEM_WORDS * 4)     // 71168

__device__ __forceinline__ void cp16(uint32_t dst, const void* src) {
    asm volatile("cp.async.cg.shared.global [%0], [%1], 16;\n"
                 :: "r"(dst), "l"(src));
}

__global__ __launch_bounds__(256, 2) void fused_kernel(
    const float* __restrict__ input,
    const float* __restrict__ offset,
    const float* __restrict__ mask,
    const float* __restrict__ bias,
    float* __restrict__ out)
{
    extern __shared__ uint32_t smem[];
    uint32_t* As0   = smem;                                   // [3][BK][LDA]
    uint32_t* Bs0   = smem + NSTG_A * TILE_WORDS;             // [2][BK][LDA]
    uint2*    moff  = reinterpret_cast<uint2*>(smem + NSTG_A * TILE_WORDS + 2 * TILE_WORDS);
    float4*   mw    = reinterpret_cast<float4*>(smem + NSTG_A * TILE_WORDS + 2 * TILE_WORDS + META_OFF_WORDS);

    const int b  = blockIdx.z;
    const int n0 = blockIdx.x * 128;

    const int tid  = threadIdx.x;
    const int wid  = tid >> 5;
    const int lane = tid & 31;
    const int wm = wid & 1;
    const int wn = wid >> 1;
    const int m_base = wm * 64;
    const int n_base = wn * 32;
    const int qr = lane >> 2;
    const int qc = lane & 3;

    // A cp.async mapping (16 x 128 tile, 2 float4 per thread)
    const int ar = tid >> 5;          // 0..7
    const int ac = (tid & 31) * 4;    // 0..124

    // B fill mapping: row br (0..15), pixels bc + 16*j
    const int br = tid >> 4;
    const int bc = tid & 15;

    uint32_t smem_u32 = (uint32_t)__cvta_generic_to_shared(smem);
    const uint32_t a_smem = smem_u32;
    const float* inb_base = input + (size_t)b * CIN * HH * WW;

    float acc[4][4][4];
    #pragma unroll
    for (int mi = 0; mi < 4; mi++)
        #pragma unroll
        for (int ni = 0; ni < 4; ni++)
            #pragma unroll
            for (int c = 0; c < 4; c++) acc[mi][ni][c] = 0.f;

    const int NK = MK / BK;   // 72

    auto issue_a = [&](int s, int kt) {
        uint32_t ad = a_smem + (uint32_t)(s * TILE_WORDS + ar * LDA + ac) * 4;
        const float* asrc = g_wt + (size_t)(kt + ar) * COUT + ac;
        cp16(ad,               asrc);
        cp16(ad + 8 * LDA * 4, asrc + (size_t)8 * COUT);
    };

    // B gather: issue 16 LDGs for 4 pixels (group j0) of tile starting at kt
    auto b_issue = [&](int kt, int j0, float* v) {
        int m = kt + br;
        int c = m / 9;
        int k = m - 9 * c;
        const float* ic = inb_base + (size_t)c * (HH * WW);
        const uint2* mo = moff + k * 128;
        #pragma unroll
        for (int j = 0; j < 4; j++) {
            int pl = bc + 16 * (j0 + j);
            uint2 o = mo[pl];
            v[j * 4 + 0] = __ldg(ic + (o.x & 0xffff));
            v[j * 4 + 1] = __ldg(ic + (o.x >> 16));
            v[j * 4 + 2] = __ldg(ic + (o.y & 0xffff));
            v[j * 4 + 3] = __ldg(ic + (o.y >> 16));
        }
    };

    auto b_consume = [&](int nb, int kt, int j0, const float* v) {
        int m = kt + br;
        int c = m / 9;
        int k = m - 9 * c;
        uint32_t* dst = Bs0 + nb * TILE_WORDS + br * LDA;
        const float4* mv = mw + k * 128;
        #pragma unroll
        for (int j = 0; j < 4; j++) {
            int pl = bc + 16 * (j0 + j);
            float4 w = mv[pl];
            float val = w.x * v[j * 4 + 0] + w.y * v[j * 4 + 1]
                      + w.z * v[j * 4 + 2] + w.w * v[j * 4 + 3];
            dst[pl] = f2tf32(val);
        }
    };

    auto mma_step = [&](const uint32_t* As_, const uint32_t* Bs_, int k0) {
        uint32_t afr[4][4];
        uint32_t bfr[4][2];
        #pragma unroll
        for (int mi = 0; mi < 4; mi++) {
            int r = m_base + mi * 16 + qr;
            afr[mi][0] = As_[(k0 + qc) * LDA + r];
            afr[mi][1] = As_[(k0 + qc) * LDA + r + 8];
            afr[mi][2] = As_[(k0 + qc + 4) * LDA + r];
            afr[mi][3] = As_[(k0 + qc + 4) * LDA + r + 8];
        }
        #pragma unroll
        for (int ni = 0; ni < 4; ni++) {
            int cidx = n_base + ni * 8 + qr;
            bfr[ni][0] = Bs_[(k0 + qc) * LDA + cidx];
            bfr[ni][1] = Bs_[(k0 + qc + 4) * LDA + cidx];
        }
        #pragma unroll
        for (int mi = 0; mi < 4; mi++)
            #pragma unroll
            for (int ni = 0; ni < 4; ni++) {
                asm volatile(
                    "mma.sync.aligned.m16n8k8.row.col.f32.tf32.tf32.f32 "
                    "{%0,%1,%2,%3}, {%4,%5,%6,%7}, {%8,%9}, {%0,%1,%2,%3};\n"
                    : "+f"(acc[mi][ni][0]), "+f"(acc[mi][ni][1]),
                      "+f"(acc[mi][ni][2]), "+f"(acc[mi][ni][3])
                    : "r"(afr[mi][0]), "r"(afr[mi][1]),
                      "r"(afr[mi][2]), "r"(afr[mi][3]),
                      "r"(bfr[ni][0]), "r"(bfr[ni][1]));
            }
    };

    // ---- prologue ----
    issue_a(0, 0);
    asm volatile("cp.async.commit_group;\n");
    issue_a(1, BK);
    asm volatile("cp.async.commit_group;\n");

    // metadata: 4 corner offsets + 4 mask-folded weights per (k, p_local)
    for (int idx = tid; idx < KK * 128; idx += 256) {
        int k  = idx >> 7;
        int pl = idx & 127;
        int p  = n0 + pl;
        int y  = p >> 6;
        int x  = p & 63;

        float offy = offset[((size_t)b * 2 * KK + 2 * k) * PP + p];
        float offx = offset[((size_t)b * 2 * KK + 2 * k + 1) * PP + p];
        float mval = mask[((size_t)b * KK + k) * PP + p];

        float py = offy + (float)(y - 1 + k / KHW);
        float px = offx + (float)(x - 1 + k % KHW);

        float y0f = floorf(py), x0f = floorf(px);
        float ly = py - y0f, lx = px - x0f;
        int y0 = (int)y0f, x0 = (int)x0f;
        int y1 = y0 + 1, x1 = x0 + 1;

        bool vy0 = (y0 >= 0) & (y0 < HH);
        bool vy1 = (y1 >= 0) & (y1 < HH);
        bool vx0 = (x0 >= 0) & (x0 < WW);
        bool vx1 = (x1 >= 0) & (x1 < WW);

        int cy0 = min(max(y0, 0), HH - 1), cy1 = min(max(y1, 0), HH - 1);
        int cx0 = min(max(x0, 0), WW - 1), cx1 = min(max(x1, 0), WW - 1);
        unsigned o00 = cy0 * WW + cx0, o01 = cy0 * WW + cx1;
        unsigned o10 = cy1 * WW + cx0, o11 = cy1 * WW + cx1;

        float w00 = (1.f - ly) * (1.f - lx) * ((vy0 & vx0) ? 1.f : 0.f) * mval;
        float w01 = (1.f - ly) * lx         * ((vy0 & vx1) ? 1.f : 0.f) * mval;
        float w10 = ly * (1.f - lx)         * ((vy1 & vx0) ? 1.f : 0.f) * mval;
        float w11 = ly * lx                 * ((vy1 & vx1) ? 1.f : 0.f) * mval;

        moff[idx] = make_uint2(o00 | (o01 << 16), o10 | (o11 << 16));
        mw[idx]   = make_float4(w00, w01, w10, w11);
    }
    __syncthreads();   // metadata visible

    float vbuf[16];

    // fill B tile 0
    b_issue(0, 0, vbuf);
    b_consume(0, 0, 0, vbuf);
    b_issue(0, 4, vbuf);
    b_consume(0, 0, 4, vbuf);
    __syncthreads();   // B0 ready

    for (int i = 0; i < NK; i++) {
        if (i + 2 < NK) issue_a((i + 2) % NSTG_A, (i + 2) * BK);
        asm volatile("cp.async.commit_group;\n");

        const bool prep = (i + 1 < NK);
        const int nkt = (i + 1) * BK;
        const int nb  = (i + 1) & 1;

        if (prep) b_issue(nkt, 0, vbuf);          // gathers in flight...

        asm volatile("cp.async.wait_group 2;\n"); // A stage i ready

        const uint32_t* As_ = As0 + (size_t)(i % NSTG_A) * TILE_WORDS;
        const uint32_t* Bs_ = Bs0 + (size_t)(i & 1) * TILE_WORDS;

        mma_step(As_, Bs_, 0);                    // ...hidden under MMA

        if (prep) {
            b_consume(nb, nkt, 0, vbuf);
            b_issue(nkt, 4, vbuf);
        }

        mma_step(As_, Bs_, 8);

        if (prep) b_consume(nb, nkt, 4, vbuf);

        __syncthreads();
    }

    // epilogue
    float* outb = out + (size_t)b * COUT * PP;
    const int cr = lane >> 2;
    const int cc = (lane & 3) * 2;
    #pragma unroll
    for (int mi = 0; mi < 4; mi++) {
        int row = m_base + mi * 16 + cr;
        float bv0 = bias[row];
        float bv1 = bias[row + 8];
        #pragma unroll
        for (int ni = 0; ni < 4; ni++) {
            int col = n0 + n_base + ni * 8 + cc;
            float2 v0 = make_float2(acc[mi][ni][0] + bv0, acc[mi][ni][1] + bv0);
            float2 v1 = make_float2(acc[mi][ni][2] + bv1, acc[mi][ni][3] + bv1);
            *reinterpret_cast<float2*>(outb + (size_t)row * PP + col)       = v0;
            *reinterpret_cast<float2*>(outb + (size_t)(row + 8) * PP + col) = v1;
        }
    }
}

extern "C" void kernel_launch(void* const* d_in, const int* in_sizes, int n_in,
                              void* d_out, int out_size)
{
    const float* input  = (const float*)d_in[0];
    const float* offset = (const float*)d_in[1];
    const float* mask   = (const float*)d_in[2];
    const float* weight = (const float*)d_in[3];
    const float* bias   = (const float*)d_in[4];
    float* out = (float*)d_out;

    wprep_kernel<<<(MK * COUT + 255) / 256, 256>>>(weight);

    cudaFuncSetAttribute(fused_kernel,
                         cudaFuncAttributeMaxDynamicSharedMemorySize, SMEM_BYTES);
    dim3 grid(PP / 128, 1, BB);               // (32, 1, 8)
    fused_kernel<<<grid, 256, SMEM_BYTES>>>(input, offset, mask, bias, out);
}

// round 14
// speedup vs baseline: 1.5950x; 1.5309x over previous
#include <cuda_runtime.h>
#include <cuda_fp16.h>
#include <math.h>
#include <stdint.h>

#define BB 8
#define CIN 128
#define COUT 128
#define HH 64
#define WW 64
#define KHW 3
#define KK 9
#define PP 4096            // Ho*Wo
#define MK 1152            // Cin*K  (reduction dim, reordered as m' = k*128 + c)
#define WPAIR 576          // MK/2
#define NKT 36             // MK/32 k-tiles

// Packed cols: half2(channel c, c+1) at row w = k*64 + c/2.  75.5 MB
__device__ uint32_t g_colsp[(size_t)BB * WPAIR * PP];
// Pre-tiled weights: [ktile][co][16 words], word j = half2(m'=kt*32+2j, +1)
__device__ uint32_t g_wtp[(size_t)NKT * COUT * 16];

// ---------------------------------------------------------------------------
// Weight prep: reorder to m' = k*128 + c, convert to half2 pairs, tile for
// the GEMM's cp.async A loads.
// ---------------------------------------------------------------------------
__global__ __launch_bounds__(256) void wprep_kernel(const float* __restrict__ Wt)
{
    int idx = blockIdx.x * blockDim.x + threadIdx.x;
    if (idx >= NKT * COUT * 16) return;
    int kt = idx >> 11;            // /(128*16)
    int co = (idx >> 4) & 127;
    int j  = idx & 15;
    int m0 = kt * 32 + 2 * j;      // even m'
    int k  = m0 >> 7;              // m' = k*128 + c
    int c  = m0 & 127;             // even
    float w0 = Wt[(size_t)co * MK + c * KK + k];
    float w1 = Wt[(size_t)co * MK + (c + 1) * KK + k];
    __half2 h = __halves2half2(__float2half_rn(w0), __float2half_rn(w1));
    g_wtp[idx] = *reinterpret_cast<uint32_t*>(&h);
}

// ---------------------------------------------------------------------------
// Deformable im2col -> packed half2 cols.
// Thread owns (b, k, p); bilinear metadata computed once, reused for 128
// channels; channels paired (c, c+1) into one half2 STG.32.
// ---------------------------------------------------------------------------
__global__ __launch_bounds__(256) void im2col_kernel(
    const float* __restrict__ input,
    const float* __restrict__ offset,
    const float* __restrict__ mask)
{
    int gid = blockIdx.x * blockDim.x + threadIdx.x;
    if (gid >= BB * KK * PP) return;
    int p = gid & (PP - 1);
    int t = gid >> 12;
    int k = t % KK;
    int b = t / KK;
    int y = p >> 6;
    int x = p & 63;

    float offy = offset[((size_t)b * 2 * KK + 2 * k) * PP + p];
    float offx = offset[((size_t)b * 2 * KK + 2 * k + 1) * PP + p];
    float mval = mask[((size_t)b * KK + k) * PP + p];

    float py = offy + (float)(y - 1 + k / KHW);
    float px = offx + (float)(x - 1 + k % KHW);

    float y0f = floorf(py), x0f = floorf(px);
    float ly = py - y0f, lx = px - x0f;
    int y0 = (int)y0f, x0 = (int)x0f;
    int y1 = y0 + 1, x1 = x0 + 1;

    bool vy0 = (y0 >= 0) & (y0 < HH);
    bool vy1 = (y1 >= 0) & (y1 < HH);
    bool vx0 = (x0 >= 0) & (x0 < WW);
    bool vx1 = (x1 >= 0) & (x1 < WW);

    int cy0 = min(max(y0, 0), HH - 1), cy1 = min(max(y1, 0), HH - 1);
    int cx0 = min(max(x0, 0), WW - 1), cx1 = min(max(x1, 0), WW - 1);
    int o00 = cy0 * WW + cx0, o01 = cy0 * WW + cx1;
    int o10 = cy1 * WW + cx0, o11 = cy1 * WW + cx1;

    float w00 = (1.f - ly) * (1.f - lx) * ((vy0 & vx0) ? 1.f : 0.f) * mval;
    float w01 = (1.f - ly) * lx         * ((vy0 & vx1) ? 1.f : 0.f) * mval;
    float w10 = ly * (1.f - lx)         * ((vy1 & vx0) ? 1.f : 0.f) * mval;
    float w11 = ly * lx                 * ((vy1 & vx1) ? 1.f : 0.f) * mval;

    const float* inb = input + (size_t)b * CIN * HH * WW;
    uint32_t* outp = g_colsp + ((size_t)b * WPAIR + (size_t)k * 64) * PP + p;

    #pragma unroll 2
    for (int c2 = 0; c2 < 64; c2++) {
        const float* ic0 = inb + (size_t)(2 * c2) * (HH * WW);
        const float* ic1 = ic0 + HH * WW;
        float v0 = w00 * __ldg(ic0 + o00) + w01 * __ldg(ic0 + o01)
                 + w10 * __ldg(ic0 + o10) + w11 * __ldg(ic0 + o11);
        float v1 = w00 * __ldg(ic1 + o00) + w01 * __ldg(ic1 + o01)
                 + w10 * __ldg(ic1 + o10) + w11 * __ldg(ic1 + o11);
        __half2 h = __halves2half2(__float2half_rn(v0), __float2half_rn(v1));
        outp[(size_t)c2 * PP] = *reinterpret_cast<uint32_t*>(&h);
    }
}

// ---------------------------------------------------------------------------
// FP16 tensor-core GEMM (mma.m16n8k16, fp32 acc), cp.async 3-stage pipeline.
// Block tile 128(co) x 128(p) x 32(m'), 256 threads, warp tile 64x32.
// A smem: [co][16 words+pad], word = k-pair half2.  B smem: [16 w][128 p words].
// ---------------------------------------------------------------------------

#define BK 32
#define AST 20                 // A smem row stride (words); banks 20*qr+qc distinct
#define BST 136                // B smem row stride (words); banks 8*qc+qr distinct
#define AW (128 * AST)         // 2560 words / stage
#define BW (16 * BST)          // 2176 words / stage
#define NSTG 3
#define SMEM_BYTES ((NSTG * (AW + BW)) * 4)   // 56832

__device__ __forceinline__ void cp16(uint32_t dst, const void* src) {
    asm volatile("cp.async.cg.shared.global [%0], [%1], 16;\n"
                 :: "r"(dst), "l"(src));
}

__global__ __launch_bounds__(256, 2) void gemm_f16_kernel(
    const float* __restrict__ bias,
    float* __restrict__ out)          // [B][128][4096]
{
    extern __shared__ uint32_t smem[];
    uint32_t* As0 = smem;                   // [NSTG][AW]
    uint32_t* Bs0 = smem + NSTG * AW;       // [NSTG][BW]

    const int b  = blockIdx.z;
    const int n0 = blockIdx.x * 128;
    const uint32_t* Bsrc = g_colsp + (size_t)b * WPAIR * PP;

    const int tid  = threadIdx.x;
    const int wid  = tid >> 5;
    const int lane = tid & 31;
    const int wm = wid & 1;
    const int wn = wid >> 1;
    const int m_base = wm * 64;
    const int n_base = wn * 32;
    const int qr = lane >> 2;
    const int qc = lane & 3;

    // cp.async mappings: A: 512 chunks (128 co x 4), B: 512 chunks (16 w x 32)
    const int a_co = tid >> 1;
    const int a_ch = (tid & 1) * 2;       // chunks a_ch, a_ch+1
    const int b_w  = tid >> 4;
    const int b_ch = (tid & 15) * 2;      // chunks b_ch, b_ch+1

    uint32_t smem_u32 = (uint32_t)__cvta_generic_to_shared(smem);
    const uint32_t a_smem = smem_u32;
    const uint32_t b_smem = smem_u32 + NSTG * AW * 4;

    float acc[4][4][4];
    #pragma unroll
    for (int mi = 0; mi < 4; mi++)
        #pragma unroll
        for (int ni = 0; ni < 4; ni++)
            #pragma unroll
            for (int c = 0; c < 4; c++) acc[mi][ni][c] = 0.f;

    auto issue = [&](int s, int i) {
        // A
        const uint32_t* asrc = g_wtp + ((size_t)i * 128 + a_co) * 16;
        uint32_t ad = a_smem + (uint32_t)(s * AW + a_co * AST) * 4;
        cp16(ad + (a_ch    ) * 16, asrc + (a_ch    ) * 4);
        cp16(ad + (a_ch + 1) * 16, asrc + (a_ch + 1) * 4);
        // B
        const uint32_t* bsrc = Bsrc + (size_t)(i * 16 + b_w) * PP + n0;
        uint32_t bd = b_smem + (uint32_t)(s * BW + b_w * BST) * 4;
        cp16(bd + (b_ch    ) * 16, bsrc + (b_ch    ) * 4);
        cp16(bd + (b_ch + 1) * 16, bsrc + (b_ch + 1) * 4);
    };

    issue(0, 0);
    asm volatile("cp.async.commit_group;\n");
    issue(1, 1);
    asm volatile("cp.async.commit_group;\n");

    for (int i = 0; i < NKT; i++) {
        if (i + 2 < NKT) issue((i + 2) % NSTG, i + 2);
        asm volatile("cp.async.commit_group;\n");
        asm volatile("cp.async.wait_group 2;\n");
        __syncthreads();

        const uint32_t* As_ = As0 + (size_t)(i % NSTG) * AW;
        const uint32_t* Bs_ = Bs0 + (size_t)(i % NSTG) * BW;

        #pragma unroll
        for (int ks = 0; ks < 2; ks++) {
            const int wb = ks * 8;
            uint32_t afr[4][4];
            uint32_t bfr[4][2];
            #pragma unroll
            for (int mi = 0; mi < 4; mi++) {
                int r = m_base + mi * 16 + qr;
                afr[mi][0] = As_[(r    ) * AST + wb + qc];
                afr[mi][1] = As_[(r + 8) * AST + wb + qc];
                afr[mi][2] = As_[(r    ) * AST + wb + qc + 4];
                afr[mi][3] = As_[(r + 8) * AST + wb + qc + 4];
            }
            #pragma unroll
            for (int ni = 0; ni < 4; ni++) {
                int n = n_base + ni * 8 + qr;
                bfr[ni][0] = Bs_[(wb + qc    ) * BST + n];
                bfr[ni][1] = Bs_[(wb + qc + 4) * BST + n];
            }
            #pragma unroll
            for (int mi = 0; mi < 4; mi++)
                #pragma unroll
                for (int ni = 0; ni < 4; ni++) {
                    asm volatile(
                        "mma.sync.aligned.m16n8k16.row.col.f32.f16.f16.f32 "
                        "{%0,%1,%2,%3}, {%4,%5,%6,%7}, {%8,%9}, {%0,%1,%2,%3};\n"
                        : "+f"(acc[mi][ni][0]), "+f"(acc[mi][ni][1]),
                          "+f"(acc[mi][ni][2]), "+f"(acc[mi][ni][3])
                        : "r"(afr[mi][0]), "r"(afr[mi][1]),
                          "r"(afr[mi][2]), "r"(afr[mi][3]),
                          "r"(bfr[ni][0]), "r"(bfr[ni][1]));
                }
        }
        __syncthreads();
    }

    // epilogue (same acc layout as m16n8 f32: c0/c1 row r, c2/c3 row r+8)
    float* outb = out + (size_t)b * COUT * PP;
    const int cr = lane >> 2;
    const int cc = (lane & 3) * 2;
    #pragma unroll
    for (int mi = 0; mi < 4; mi++) {
        int row = m_base + mi * 16 + cr;
        float bv0 = bias[row];
        float bv1 = bias[row + 8];
        #pragma unroll
        for (int ni = 0; ni < 4; ni++) {
            int col = n0 + n_base + ni * 8 + cc;
            float2 v0 = make_float2(acc[mi][ni][0] + bv0, acc[mi][ni][1] + bv0);
            float2 v1 = make_float2(acc[mi][ni][2] + bv1, acc[mi][ni][3] + bv1);
            *reinterpret_cast<float2*>(outb + (size_t)row * PP + col)       = v0;
            *reinterpret_cast<float2*>(outb + (size_t)(row + 8) * PP + col) = v1;
        }
    }
}

extern "C" void kernel_launch(void* const* d_in, const int* in_sizes, int n_in,
                              void* d_out, int out_size)
{
    const float* input  = (const float*)d_in[0];
    const float* offset = (const float*)d_in[1];
    const float* mask   = (const float*)d_in[2];
    const float* weight = (const float*)d_in[3];
    const float* bias   = (const float*)d_in[4];
    float* out = (float*)d_out;

    wprep_kernel<<<(NKT * COUT * 16 + 255) / 256, 256>>>(weight);

    int total = BB * KK * PP;                 // 294912
    im2col_kernel<<<(total + 255) / 256, 256>>>(input, offset, mask);

    cudaFuncSetAttribute(gemm_f16_kernel,
                         cudaFuncAttributeMaxDynamicSharedMemorySize, SMEM_BYTES);
    dim3 grid(PP / 128, 1, BB);               // (32, 1, 8)
    gemm_f16_kernel<<<grid, 256, SMEM_BYTES>>>(bias, out);
}